// round 4
// baseline (speedup 1.0000x reference)
#include <cuda_runtime.h>

// x_seq (T=16, N=8, C=64, H=64, W=64) fp32; conv_weight (64,64,3,3) fp32.
// z = conv3x3(pad=1, no bias) over B=T*N=128 images, then LIF scan over T.
#define T_  16
#define NB  8
#define C_  64
#define H_  64
#define W_  64
#define B_  (T_ * NB)          // 128 images
#define HW_ (H_ * W_)          // 4096
#define CHW (C_ * HW_)         // 262144
#define INNER (NB * CHW)       // 2097152 elements per timestep

#define TS 16                   // spatial tile 16x16
#define CIN_CHUNK 16            // cin staged in smem per sync
#define COUT_PER  16            // couts per block (4 groups)

// Scratch for conv output z (T,N,C,H,W) — static device global (no allocation).
__device__ float g_z[(size_t)B_ * CHW];

// ---------------------------------------------------------------------------
// Direct 3x3 conv. One block = one image x one 16x16 tile x 16 output chans.
// Precision scheme: fp32 FFMA over 4-cin chunks (36 taps), chunk sums folded
// into a double total (exact combine). Cuts accumulation error ~6x vs a flat
// 576-term fp32 chain, so spike threshold flips vs the fp32 reference are
// dominated by the reference's own rounding.
// Weights staged in smem transposed to [ci][tap][cout] so inner weight reads
// are warp-uniform (broadcast) LDS.128.
// ---------------------------------------------------------------------------
__global__ __launch_bounds__(256, 2)
void conv3x3_kernel(const float* __restrict__ x, const float* __restrict__ w) {
    __shared__ float xs[CIN_CHUNK * 18 * 18];        // 20736 B
    __shared__ float ws[CIN_CHUNK * 9 * COUT_PER];   //  9216 B

    const int tile = blockIdx.x;          // 0..15 (4x4 tiles)
    const int b    = blockIdx.y;          // 0..127
    const int cg   = blockIdx.z;          // 0..3 cout group
    const int tx = tile & 3, ty = tile >> 2;
    const int h0 = ty * TS, w0 = tx * TS;
    const int tid = threadIdx.x;
    const int px = tid & 15, py = tid >> 4;

    double accd[COUT_PER];
#pragma unroll
    for (int i = 0; i < COUT_PER; i++) accd[i] = 0.0;

    for (int cc = 0; cc < C_; cc += CIN_CHUNK) {
        // Cooperative load: input tile with halo (zero-padded at borders)
        for (int idx = tid; idx < CIN_CHUNK * 18 * 18; idx += 256) {
            int ci  = idx / 324;
            int rem = idx - ci * 324;
            int r = rem / 18, c = rem - r * 18;
            int gh = h0 + r - 1, gw = w0 + c - 1;
            float v = 0.0f;
            if ((unsigned)gh < (unsigned)H_ && (unsigned)gw < (unsigned)W_)
                v = x[(size_t)b * CHW + (size_t)(cc + ci) * HW_ + gh * W_ + gw];
            xs[idx] = v;
        }
        // Cooperative load: weights transposed to ws[(ci*9 + k)*16 + co]
        for (int idx = tid; idx < CIN_CHUNK * 9 * COUT_PER; idx += 256) {
            int ci  = idx / (9 * COUT_PER);
            int rem = idx - ci * (9 * COUT_PER);
            int k  = rem / COUT_PER;
            int co = rem - k * COUT_PER;
            ws[idx] = w[((size_t)(cg * COUT_PER + co) * C_ + (cc + ci)) * 9 + k];
        }
        __syncthreads();

#pragma unroll 1
        for (int c4 = 0; c4 < CIN_CHUNK / 4; c4++) {
            float accf[COUT_PER];
#pragma unroll
            for (int i = 0; i < COUT_PER; i++) accf[i] = 0.0f;

#pragma unroll
            for (int ci4 = 0; ci4 < 4; ci4++) {
                const int ci = c4 * 4 + ci4;
                float xw[9];
                const float* xb = &xs[ci * 324 + py * 18 + px];
#pragma unroll
                for (int kh = 0; kh < 3; kh++)
#pragma unroll
                    for (int kw = 0; kw < 3; kw++)
                        xw[kh * 3 + kw] = xb[kh * 18 + kw];

#pragma unroll
                for (int k = 0; k < 9; k++) {
                    float xv = xw[k];
                    const float4* wp = (const float4*)&ws[(ci * 9 + k) * COUT_PER];
#pragma unroll
                    for (int q = 0; q < COUT_PER / 4; q++) {
                        float4 wv = wp[q];
                        accf[q * 4 + 0] = __fmaf_rn(xv, wv.x, accf[q * 4 + 0]);
                        accf[q * 4 + 1] = __fmaf_rn(xv, wv.y, accf[q * 4 + 1]);
                        accf[q * 4 + 2] = __fmaf_rn(xv, wv.z, accf[q * 4 + 2]);
                        accf[q * 4 + 3] = __fmaf_rn(xv, wv.w, accf[q * 4 + 3]);
                    }
                }
            }
            // Exact fold of the 4-cin chunk into the double total.
#pragma unroll
            for (int i = 0; i < COUT_PER; i++) accd[i] += (double)accf[i];
        }
        __syncthreads();
    }

    const int h = h0 + py, ww = w0 + px;
#pragma unroll
    for (int co = 0; co < COUT_PER; co++) {
        g_z[(size_t)b * CHW + (size_t)(cg * COUT_PER + co) * HW_ + h * W_ + ww] =
            (float)accd[co];
    }
}

// ---------------------------------------------------------------------------
// LIF scan over T: v += (x - v)/2 ; spike = (v >= 1); hard reset to 0.
// One thread per (n,c,h,w) neuron, sequential over T. Fully coalesced.
// Arithmetic is bit-identical to the reference given identical z
// (/2.0 == *0.5 exact; V_RESET == 0).
// ---------------------------------------------------------------------------
__global__ __launch_bounds__(256)
void lif_kernel(float* __restrict__ out) {
    int i = blockIdx.x * blockDim.x + threadIdx.x;   // 0 .. INNER-1
    float v = 0.0f;
#pragma unroll
    for (int t = 0; t < T_; t++) {
        float xv = g_z[(size_t)t * INNER + i];
        v = v + (xv - v) * 0.5f;
        float s = (v >= 1.0f) ? 1.0f : 0.0f;
        out[(size_t)t * INNER + i] = s;
        if (v >= 1.0f) v = 0.0f;
    }
}

extern "C" void kernel_launch(void* const* d_in, const int* in_sizes, int n_in,
                              void* d_out, int out_size) {
    const float* x = (const float*)d_in[0];   // x_seq (16,8,64,64,64)
    const float* w = (const float*)d_in[1];   // conv_weight (64,64,3,3)
    float* out = (float*)d_out;

    dim3 grid(16, B_, 4);   // 4x4 tiles, 128 images, 4 cout groups
    conv3x3_kernel<<<grid, 256>>>(x, w);
    lif_kernel<<<INNER / 256, 256>>>(out);
}